// round 13
// baseline (speedup 1.0000x reference)
#include <cuda_runtime.h>
#include <cuda_fp16.h>
#include <cstdint>

#define NTH     128
#define PT      64
#define NPT     156
#define NTILES  (128 * NPT)
#define PLEN    9984
#define LL      10000
#define NK      128

// smem layout (bytes)
#define XS_OFF  0                 // 2 x 96 float4 (80 used) = 3072B
#define W_OFF   3072              // 64KB: W'[k=128][s=256] fp16, blocked SW128
#define P_OFF   68608             // 3840B: P[80 rows][16 cc] fp16, 48B row stride
#define SMEM_TOTAL 72448

static __device__ __forceinline__ uint32_t s2u(const void* p) {
    uint32_t a;
    asm("{ .reg .u64 t; cvta.to.shared.u64 t, %1; cvt.u32.u64 %0, t; }" : "=r"(a) : "l"(p));
    return a;
}

// Blocked SW128 atom layout for W [128 rows x 256 halves]; atom = 8 rows x 128B, rstride 16.
static __device__ __forceinline__ uint32_t wa(int row, int s) {
    uint32_t byte = (uint32_t)((((row >> 3) + ((s >> 6) << 4)) << 10) + ((row & 7) << 7) + ((s & 63) << 1));
    return byte ^ ((byte >> 3) & 0x70);
}
// Unswizzled byte offset (incremental addressing adds here, then XORs the mask)
static __device__ __forceinline__ uint32_t wa_u(int row, int s) {
    return (uint32_t)((((row >> 3) + ((s >> 6) << 4)) << 10) + ((row & 7) << 7) + ((s & 63) << 1));
}

static __device__ __forceinline__ uint32_t f2h2(float a, float b) {
    __half2 h = __floats2half2_rn(a, b);
    return *reinterpret_cast<uint32_t*>(&h);
}

static __device__ __forceinline__ void ldsm4(uint32_t (&r)[4], uint32_t addr) {
    asm volatile("ldmatrix.sync.aligned.m8n8.x4.shared.b16 {%0,%1,%2,%3}, [%4];"
        : "=r"(r[0]), "=r"(r[1]), "=r"(r[2]), "=r"(r[3]) : "r"(addr));
}

static __device__ __forceinline__ void sts128(uint32_t addr, uint4 v) {
    asm volatile("st.shared.v4.b32 [%0], {%1,%2,%3,%4};"
        :: "r"(addr), "r"(v.x), "r"(v.y), "r"(v.z), "r"(v.w));
}

static __device__ __forceinline__ void mma16816(float (&d)[4], const uint32_t (&a)[4],
                                                uint32_t b0, uint32_t b1) {
    asm volatile("mma.sync.aligned.m16n8k16.row.col.f32.f16.f16.f32 "
        "{%0,%1,%2,%3}, {%4,%5,%6,%7}, {%8,%9}, {%0,%1,%2,%3};"
        : "+f"(d[0]), "+f"(d[1]), "+f"(d[2]), "+f"(d[3])
        : "r"(a[0]), "r"(a[1]), "r"(a[2]), "r"(a[3]), "r"(b0), "r"(b1));
}

// P row t: P[t][c1*4+c2] = x[t][c1] * x[t+1][c2]; 16 halves = 32B at t*48 (48B stride).
static __device__ __forceinline__ void build_p(uint32_t pbase, const float4* xs, int t) {
    const float4 a = xs[t], c = xs[t + 1];
    uint4 lo, hi;
    lo.x = f2h2(a.x * c.x, a.x * c.y); lo.y = f2h2(a.x * c.z, a.x * c.w);
    lo.z = f2h2(a.y * c.x, a.y * c.y); lo.w = f2h2(a.y * c.z, a.y * c.w);
    hi.x = f2h2(a.z * c.x, a.z * c.y); hi.y = f2h2(a.z * c.z, a.z * c.w);
    hi.z = f2h2(a.w * c.x, a.w * c.y); hi.w = f2h2(a.w * c.z, a.w * c.w);
    sts128(pbase + t * 48, lo);
    sts128(pbase + t * 48 + 16, hi);
}

static __device__ __forceinline__ const float4* xwin(const float* x, int tile) {
    const int b = tile / NPT, p0 = (tile - b * NPT) * PT;
    return (const float4*)(x + ((size_t)b * LL + p0) * 4);
}

__global__ void __launch_bounds__(NTH, 3)
markonv_kernel(const float* __restrict__ x, const float* __restrict__ ker,
               float* __restrict__ out) {
    extern __shared__ char smem[];
    uint32_t sb = s2u(smem);
    const int tid = threadIdx.x;
    const int lane = tid & 31;
    const int wid = tid >> 5;
    const int wm = wid & 1;   // warp M (k): 2 x 64 rows
    const int wn = wid >> 1;  // warp N (p): 2 x 32 cols
    const int G = gridDim.x;

    // ---- stage W once per CTA: W'[k][s] = ker[s*128 + k] ----
    for (int idx = tid; idx < 128 * 128; idx += NTH) {
        int k = idx & 127, s = (idx >> 7) << 1;
        *(uint32_t*)(smem + W_OFF + wa(k, s)) =
            f2h2(ker[s * 128 + k], ker[s * 128 + 128 + k]);
    }

    // A (W) lane addressing: unswizzled base + per-thread XOR mask (bits 4-6).
    const int a_row = wm * 64 + (lane & 15);
    const uint32_t wbyteU = wa_u(a_row, (lane >> 4) << 3);
    const uint32_t wmask  = (uint32_t)((a_row & 7) << 4);
    // B (P) lane addressing: linear; per-kstep +48, rows +16 -> +768.
    const uint32_t pblane = (uint32_t)((wn * 32 + (lane & 7) + ((lane >> 4) << 3)) * 48
                                       + (((lane >> 3) & 1) << 4));

    int tile = blockIdx.x;
    float4 xr = make_float4(0.f, 0.f, 0.f, 0.f);

    // ---- prologue: stage xs[0], prefetch x(tile+G) ----
    if (tid < 80) {
        ((float4*)(smem + XS_OFF))[tid] = xwin(x, tile)[tid];
        if (tile + G < NTILES) xr = xwin(x, tile + G)[tid];
    }

    int n = 0;
    for (; tile < NTILES; tile += G, n++) {
        const int cb = n & 1, nb = cb ^ 1;

        __syncthreads();   // previous tile's MMA reads of P done; xs[cb] visible

        // build P from xs[cb]; publish xs[nb] for next tile
        const float4* xsc = (const float4*)(smem + XS_OFF) + cb * 96;
        if (tid < 80) {
            build_p(sb + P_OFF, xsc, tid);
            ((float4*)(smem + XS_OFF))[nb * 96 + tid] = xr;
        }
        __syncthreads();   // P + xs[nb] published

        const int b = tile / NPT;
        const int p0 = (tile - b * NPT) * PT;

        // prefetch x(tile+2G)
        if (tid < 80 && tile + 2 * G < NTILES) xr = xwin(x, tile + 2 * G)[tid];

        // ---- GEMM: D[128k x 64p] = W * V^T, V[p][16ks+cc] = P[p+ks][cc] ----
        const uint32_t pcur = sb + P_OFF + pblane;
        const uint32_t wsb  = sb + W_OFF;

        float acc[4][4][4];
        #pragma unroll
        for (int mf = 0; mf < 4; mf++)
            #pragma unroll
            for (int nf = 0; nf < 4; nf++)
                #pragma unroll
                for (int e = 0; e < 4; e++) acc[mf][nf][e] = 0.f;

        #pragma unroll
        for (int ks = 0; ks < 16; ks++) {
            uint32_t af[4][4], bf[2][4];
            const uint32_t d = (uint32_t)((ks >> 2) * 16384 + (ks & 3) * 32);
            const uint32_t ab = wsb + ((wbyteU + d) ^ wmask);
            const uint32_t bb = pcur + (uint32_t)(ks * 48);
            ldsm4(af[0], ab);
            ldsm4(af[1], ab + 2048);
            ldsm4(af[2], ab + 4096);
            ldsm4(af[3], ab + 6144);
            ldsm4(bf[0], bb);
            ldsm4(bf[1], bb + 768);
            #pragma unroll
            for (int mf = 0; mf < 4; mf++) {
                mma16816(acc[mf][0], af[mf], bf[0][0], bf[0][1]);
                mma16816(acc[mf][1], af[mf], bf[0][2], bf[0][3]);
                mma16816(acc[mf][2], af[mf], bf[1][0], bf[1][1]);
                mma16816(acc[mf][3], af[mf], bf[1][2], bf[1][3]);
            }
        }

        // ---- epilogue: direct STG.64 (rows = k, cols = consecutive p) ----
        {
            const size_t obase = ((size_t)b * NK + wm * 64) * PLEN + p0 + wn * 32;
            const int krow = lane >> 2;
            const int pcol = (lane & 3) * 2;
            #pragma unroll
            for (int mf = 0; mf < 4; mf++) {
                #pragma unroll
                for (int nf = 0; nf < 4; nf++) {
                    size_t o = obase + (size_t)(mf * 16 + krow) * PLEN + nf * 8 + pcol;
                    *(float2*)(out + o)            = make_float2(acc[mf][nf][0], acc[mf][nf][1]);
                    *(float2*)(out + o + 8 * PLEN) = make_float2(acc[mf][nf][2], acc[mf][nf][3]);
                }
            }
        }
    }
}

extern "C" void kernel_launch(void* const* d_in, const int* in_sizes, int n_in,
                              void* d_out, int out_size) {
    static int nsm = 0;
    if (nsm == 0) {
        int dev = 0;
        cudaGetDevice(&dev);
        if (cudaDeviceGetAttribute(&nsm, cudaDevAttrMultiProcessorCount, dev) != cudaSuccess || nsm <= 0)
            nsm = 148;
        cudaFuncSetAttribute(markonv_kernel, cudaFuncAttributeMaxDynamicSharedMemorySize, SMEM_TOTAL);
    }
    markonv_kernel<<<3 * nsm, NTH, SMEM_TOTAL>>>(
        (const float*)d_in[0], (const float*)d_in[1], (float*)d_out);
}

// round 14
// speedup vs baseline: 1.0334x; 1.0334x over previous
#include <cuda_runtime.h>
#include <cuda_fp16.h>
#include <cstdint>

#define NTH     256
#define PT      128
#define NPT     78
#define NTILES  (128 * NPT)
#define PLEN    9984
#define LL      10000
#define NK      128

// smem layout (bytes)
#define XS_OFF  0                 // 2 x 160 float4 (144 used) = 5120B
#define W_OFF   5120              // 64KB: W'[k=128][s=256] fp16, blocked SW128
#define P0_OFF  70656             // 2 x 6912B: P[144 rows][16 cc] fp16, 48B row stride
#define PSZ     6912
#define SMEM_TOTAL 84480

static __device__ __forceinline__ uint32_t s2u(const void* p) {
    uint32_t a;
    asm("{ .reg .u64 t; cvta.to.shared.u64 t, %1; cvt.u32.u64 %0, t; }" : "=r"(a) : "l"(p));
    return a;
}

// Blocked SW128 atom layout for W [128 rows x 256 halves]; atom = 8 rows x 128B, rstride 16.
static __device__ __forceinline__ uint32_t wa(int row, int s) {
    uint32_t byte = (uint32_t)((((row >> 3) + ((s >> 6) << 4)) << 10) + ((row & 7) << 7) + ((s & 63) << 1));
    return byte ^ ((byte >> 3) & 0x70);
}
// Unswizzled byte offset (incremental addressing adds here, then XORs the mask)
static __device__ __forceinline__ uint32_t wa_u(int row, int s) {
    return (uint32_t)((((row >> 3) + ((s >> 6) << 4)) << 10) + ((row & 7) << 7) + ((s & 63) << 1));
}

static __device__ __forceinline__ uint32_t f2h2(float a, float b) {
    __half2 h = __floats2half2_rn(a, b);
    return *reinterpret_cast<uint32_t*>(&h);
}

static __device__ __forceinline__ void ldsm4(uint32_t (&r)[4], uint32_t addr) {
    asm volatile("ldmatrix.sync.aligned.m8n8.x4.shared.b16 {%0,%1,%2,%3}, [%4];"
        : "=r"(r[0]), "=r"(r[1]), "=r"(r[2]), "=r"(r[3]) : "r"(addr));
}

static __device__ __forceinline__ void sts128(uint32_t addr, uint4 v) {
    asm volatile("st.shared.v4.b32 [%0], {%1,%2,%3,%4};"
        :: "r"(addr), "r"(v.x), "r"(v.y), "r"(v.z), "r"(v.w));
}

static __device__ __forceinline__ void mma16816(float (&d)[4], const uint32_t (&a)[4],
                                                uint32_t b0, uint32_t b1) {
    asm volatile("mma.sync.aligned.m16n8k16.row.col.f32.f16.f16.f32 "
        "{%0,%1,%2,%3}, {%4,%5,%6,%7}, {%8,%9}, {%0,%1,%2,%3};"
        : "+f"(d[0]), "+f"(d[1]), "+f"(d[2]), "+f"(d[3])
        : "r"(a[0]), "r"(a[1]), "r"(a[2]), "r"(a[3]), "r"(b0), "r"(b1));
}

// Half-row build unit: u = (t, h); writes P[t][8h..8h+7] = x[t][2h..2h+1] x x[t+1][0..3].
static __device__ __forceinline__ void build_half(uint32_t pbase, const float4* xs, int u) {
    const int t = u >> 1, h = u & 1;
    const float4 a = xs[t], c = xs[t + 1];
    const float a0 = h ? a.z : a.x;
    const float a1 = h ? a.w : a.y;
    uint4 v;
    v.x = f2h2(a0 * c.x, a0 * c.y); v.y = f2h2(a0 * c.z, a0 * c.w);
    v.z = f2h2(a1 * c.x, a1 * c.y); v.w = f2h2(a1 * c.z, a1 * c.w);
    sts128(pbase + t * 48 + (h << 4), v);
}

static __device__ __forceinline__ const float4* xwin(const float* x, int tile) {
    const int b = tile / NPT, p0 = (tile - b * NPT) * PT;
    return (const float4*)(x + ((size_t)b * LL + p0) * 4);
}

__global__ void __launch_bounds__(NTH, 2)
markonv_kernel(const float* __restrict__ x, const float* __restrict__ ker,
               float* __restrict__ out) {
    extern __shared__ char smem[];
    uint32_t sb = s2u(smem);
    const int tid = threadIdx.x;
    const int lane = tid & 31;
    const int wid = tid >> 5;
    const int wm = wid & 1;   // warp M (k): 2 x 64 rows
    const int wn = wid >> 1;  // warp N (p): 4 x 32 cols
    const int G = gridDim.x;

    // ---- stage W once per CTA: W'[k][s] = ker[s*128 + k] ----
    for (int idx = tid; idx < 128 * 128; idx += NTH) {
        int k = idx & 127, s = (idx >> 7) << 1;
        *(uint32_t*)(smem + W_OFF + wa(k, s)) =
            f2h2(ker[s * 128 + k], ker[s * 128 + 128 + k]);
    }

    // A (W) lane addressing: unswizzled base + per-thread XOR mask (bits 4-6).
    const int a_row = wm * 64 + (lane & 15);
    const uint32_t wbyteU = wa_u(a_row, (lane >> 4) << 3);
    const uint32_t wmask  = (uint32_t)((a_row & 7) << 4);
    // B (P) lane addressing: linear; per-kstep +48, rows +16 -> +768.
    const uint32_t pblane = (uint32_t)((wn * 32 + (lane & 7) + ((lane >> 4) << 3)) * 48
                                       + (((lane >> 3) & 1) << 4));

    int tile = blockIdx.x;
    float4 xr = make_float4(0.f, 0.f, 0.f, 0.f);

    // ---- prologue: stage xs[0], build P[0] (buffer 0), prefetch x(tile+G) ----
    {
        if (tid < 144) {
            xr = xwin(x, tile)[tid];
            ((float4*)(smem + XS_OFF))[tid] = xr;
        }
        __syncthreads();
        const float4* xs0 = (const float4*)(smem + XS_OFF);
        build_half(sb + P0_OFF, xs0, tid);
        if (tid < 32) build_half(sb + P0_OFF, xs0, 256 + tid);
        if (tid < 144 && tile + G < NTILES) xr = xwin(x, tile + G)[tid];
    }

    int n = 0;
    for (; tile < NTILES; tile += G, n++) {
        const int cb = n & 1, nb = cb ^ 1;

        // publish x window for tile+G; barrier publishes P[cb] (built last iter) and xs[nb]
        float4* xsn = (float4*)(smem + XS_OFF) + nb * 160;
        if (tid < 144) xsn[tid] = xr;
        __syncthreads();

        const int b = tile / NPT;
        const int p0 = (tile - b * NPT) * PT;

        // prefetch x(tile+2G)
        if (tid < 144 && tile + 2 * G < NTILES) xr = xwin(x, tile + 2 * G)[tid];

        // ---- GEMM over P[cb], with P[nb] build interleaved into the k-loop ----
        const uint32_t pcur = sb + P0_OFF + cb * PSZ + pblane;
        const uint32_t pnxt = sb + P0_OFF + nb * PSZ;
        const uint32_t wsb  = sb + W_OFF;

        float acc[4][4][4];
        #pragma unroll
        for (int mf = 0; mf < 4; mf++)
            #pragma unroll
            for (int nf = 0; nf < 4; nf++)
                #pragma unroll
                for (int e = 0; e < 4; e++) acc[mf][nf][e] = 0.f;

        #pragma unroll
        for (int ks = 0; ks < 16; ks++) {
            uint32_t af[4][4], bf[2][4];
            const uint32_t d = (uint32_t)((ks >> 2) * 16384 + (ks & 3) * 32);
            const uint32_t ab = wsb + ((wbyteU + d) ^ wmask);
            const uint32_t bb = pcur + (uint32_t)(ks * 48);
            ldsm4(af[0], ab);
            ldsm4(af[1], ab + 2048);
            ldsm4(af[2], ab + 4096);
            ldsm4(af[3], ab + 6144);
            ldsm4(bf[0], bb);
            ldsm4(bf[1], bb + 768);
            #pragma unroll
            for (int mf = 0; mf < 4; mf++) {
                mma16816(acc[mf][0], af[mf], bf[0][0], bf[0][1]);
                mma16816(acc[mf][1], af[mf], bf[0][2], bf[0][3]);
                mma16816(acc[mf][2], af[mf], bf[1][0], bf[1][1]);
                mma16816(acc[mf][3], af[mf], bf[1][2], bf[1][3]);
            }
            // interleave next tile's P build: 288 half-row units in 2 chunks
            if (ks == 5) build_half(pnxt, xsn, tid);
            if (ks == 11 && tid < 32) build_half(pnxt, xsn, 256 + tid);
        }

        // ---- epilogue: direct STG.64 (rows = k, cols = consecutive p) ----
        {
            const size_t obase = ((size_t)b * NK + wm * 64) * PLEN + p0 + wn * 32;
            const int krow = lane >> 2;
            const int pcol = (lane & 3) * 2;
            #pragma unroll
            for (int mf = 0; mf < 4; mf++) {
                #pragma unroll
                for (int nf = 0; nf < 4; nf++) {
                    size_t o = obase + (size_t)(mf * 16 + krow) * PLEN + nf * 8 + pcol;
                    *(float2*)(out + o)            = make_float2(acc[mf][nf][0], acc[mf][nf][1]);
                    *(float2*)(out + o + 8 * PLEN) = make_float2(acc[mf][nf][2], acc[mf][nf][3]);
                }
            }
        }
    }
}

extern "C" void kernel_launch(void* const* d_in, const int* in_sizes, int n_in,
                              void* d_out, int out_size) {
    static int nsm = 0;
    if (nsm == 0) {
        int dev = 0;
        cudaGetDevice(&dev);
        if (cudaDeviceGetAttribute(&nsm, cudaDevAttrMultiProcessorCount, dev) != cudaSuccess || nsm <= 0)
            nsm = 148;
        cudaFuncSetAttribute(markonv_kernel, cudaFuncAttributeMaxDynamicSharedMemorySize, SMEM_TOTAL);
    }
    markonv_kernel<<<2 * nsm, NTH, SMEM_TOTAL>>>(
        (const float*)d_in[0], (const float*)d_in[1], (float*)d_out);
}

// round 15
// speedup vs baseline: 1.2505x; 1.2102x over previous
#include <cuda_runtime.h>
#include <cuda_fp16.h>
#include <cstdint>

#define NTH     512
#define NPC     312               // 32-wide p chunks: 312*32 = 9984
#define TASKS   (128 * NPC * 2)   // (b, pc, wm) warp-tasks
#define PLEN    9984
#define LL      10000
#define NK      128

// smem: W 64KB (read-only after init) + per-warp double-buffered P
#define W_OFF   0
#define P_OFF   65536             // 16 warps x 2 x 2304B
#define SMEM_TOTAL (65536 + 16 * 4608)

static __device__ __forceinline__ uint32_t s2u(const void* p) {
    uint32_t a;
    asm("{ .reg .u64 t; cvta.to.shared.u64 t, %1; cvt.u32.u64 %0, t; }" : "=r"(a) : "l"(p));
    return a;
}

// Blocked SW128 atom layout for W [128 rows x 256 halves]; atom = 8 rows x 128B, rstride 16.
static __device__ __forceinline__ uint32_t wa(int row, int s) {
    uint32_t byte = (uint32_t)((((row >> 3) + ((s >> 6) << 4)) << 10) + ((row & 7) << 7) + ((s & 63) << 1));
    return byte ^ ((byte >> 3) & 0x70);
}
static __device__ __forceinline__ uint32_t wa_u(int row, int s) {
    return (uint32_t)((((row >> 3) + ((s >> 6) << 4)) << 10) + ((row & 7) << 7) + ((s & 63) << 1));
}

static __device__ __forceinline__ uint32_t f2h2(float a, float b) {
    __half2 h = __floats2half2_rn(a, b);
    return *reinterpret_cast<uint32_t*>(&h);
}

static __device__ __forceinline__ void ldsm4(uint32_t (&r)[4], uint32_t addr) {
    asm volatile("ldmatrix.sync.aligned.m8n8.x4.shared.b16 {%0,%1,%2,%3}, [%4];"
        : "=r"(r[0]), "=r"(r[1]), "=r"(r[2]), "=r"(r[3]) : "r"(addr));
}

static __device__ __forceinline__ void sts128(uint32_t addr, uint4 v) {
    asm volatile("st.shared.v4.b32 [%0], {%1,%2,%3,%4};"
        :: "r"(addr), "r"(v.x), "r"(v.y), "r"(v.z), "r"(v.w));
}

static __device__ __forceinline__ void mma16816(float (&d)[4], const uint32_t (&a)[4],
                                                uint32_t b0, uint32_t b1) {
    asm volatile("mma.sync.aligned.m16n8k16.row.col.f32.f16.f16.f32 "
        "{%0,%1,%2,%3}, {%4,%5,%6,%7}, {%8,%9}, {%0,%1,%2,%3};"
        : "+f"(d[0]), "+f"(d[1]), "+f"(d[2]), "+f"(d[3])
        : "r"(a[0]), "r"(a[1]), "r"(a[2]), "r"(a[3]), "r"(b0), "r"(b1));
}

// Build P row t from registers: P[t][c1*4+c2] = a[c1] * c[c2]; 32B at t*48.
static __device__ __forceinline__ void build_row(uint32_t pbase, int t, float4 a, float4 c) {
    uint4 lo, hi;
    lo.x = f2h2(a.x * c.x, a.x * c.y); lo.y = f2h2(a.x * c.z, a.x * c.w);
    lo.z = f2h2(a.y * c.x, a.y * c.y); lo.w = f2h2(a.y * c.z, a.y * c.w);
    hi.x = f2h2(a.z * c.x, a.z * c.y); hi.y = f2h2(a.z * c.z, a.z * c.w);
    hi.z = f2h2(a.w * c.x, a.w * c.y); hi.w = f2h2(a.w * c.z, a.w * c.w);
    sts128(pbase + t * 48, lo);
    sts128(pbase + t * 48 + 16, hi);
}

// exchange one float2 across shfl_xor(m)
static __device__ __forceinline__ void xpose_pair(float2& a, float2& b, int sel, int m) {
    float2 s = sel ? a : b;
    float2 r;
    r.x = __shfl_xor_sync(0xffffffffu, s.x, m);
    r.y = __shfl_xor_sync(0xffffffffu, s.y, m);
    if (sel) a = r; else b = r;
}

__global__ void __launch_bounds__(NTH, 1)
markonv_kernel(const float* __restrict__ x, const float* __restrict__ ker,
               float* __restrict__ out) {
    extern __shared__ char smem[];
    uint32_t sb = s2u(smem);
    const int tid = threadIdx.x;
    const int lane = tid & 31;
    const int wid = tid >> 5;

    // ---- stage W once (read-only afterwards): W'[k][s] = ker[s*128 + k] ----
    for (int idx = tid; idx < 128 * 128; idx += NTH) {
        int k = idx & 127, s = (idx >> 7) << 1;
        *(uint32_t*)(smem + W_OFF + wa(k, s)) =
            f2h2(ker[s * 128 + k], ker[s * 128 + 128 + k]);
    }
    __syncthreads();   // the ONLY block-wide barrier

    const uint32_t wsb = sb + W_OFF;
    const uint32_t mypbase = sb + P_OFF + wid * 4608;
    // B (P) lane addressing: rows in [0,16) + frag offset; per-kstep +48, +16 rows -> +768
    const uint32_t pblane_off = (uint32_t)(((lane & 7) + ((lane >> 4) << 3)) * 48
                                           + (((lane >> 3) & 1) << 4));
    const int wstride = gridDim.x * (NTH / 32);

    int n = 0;
    for (int w = blockIdx.x * (NTH / 32) + wid; w < TASKS; w += wstride, n++) {
        const int b = w / (NPC * 2);
        const int r = w - b * (NPC * 2);
        const int pc = r >> 1, wm = r & 1;
        const int p0 = pc * 32;

        // ---- build private P (rows 0..46) into buffer n&1 ----
        const uint32_t pb = mypbase + (n & 1) * 2304;
        const float4* xg = (const float4*)(x + ((size_t)b * LL + p0) * 4);
        {
            float4 a0 = xg[lane], c0 = xg[lane + 1];
            build_row(pb, lane, a0, c0);
            if (lane < 15) {
                float4 a1 = xg[32 + lane], c1 = xg[33 + lane];
                build_row(pb, 32 + lane, a1, c1);
            }
        }
        __syncwarp();

        // A (W) lane addressing for this wm half
        const int a_row = wm * 64 + (lane & 15);
        const uint32_t wbyteU = wa_u(a_row, (lane >> 4) << 3);
        const uint32_t wmask  = (uint32_t)((a_row & 7) << 4);
        const uint32_t pcur = pb + pblane_off;

        // ---- GEMM: D[64k x 32p] = W[wm] * V^T, V[p][16ks+cc] = P[p+ks][cc] ----
        float acc[4][4][4];
        #pragma unroll
        for (int mf = 0; mf < 4; mf++)
            #pragma unroll
            for (int nf = 0; nf < 4; nf++)
                #pragma unroll
                for (int e = 0; e < 4; e++) acc[mf][nf][e] = 0.f;

        #pragma unroll
        for (int ks = 0; ks < 16; ks++) {
            uint32_t af[4][4], bf[2][4];
            const uint32_t d = (uint32_t)((ks >> 2) * 16384 + (ks & 3) * 32);
            const uint32_t ab = wsb + ((wbyteU + d) ^ wmask);
            const uint32_t bb = pcur + (uint32_t)(ks * 48);
            ldsm4(af[0], ab);
            ldsm4(af[1], ab + 2048);
            ldsm4(af[2], ab + 4096);
            ldsm4(af[3], ab + 6144);
            ldsm4(bf[0], bb);
            ldsm4(bf[1], bb + 768);
            #pragma unroll
            for (int mf = 0; mf < 4; mf++) {
                mma16816(acc[mf][0], af[mf], bf[0][0], bf[0][1]);
                mma16816(acc[mf][1], af[mf], bf[0][2], bf[0][3]);
                mma16816(acc[mf][2], af[mf], bf[1][0], bf[1][1]);
                mma16816(acc[mf][3], af[mf], bf[1][2], bf[1][3]);
            }
        }

        // ---- epilogue: quad 4x4 transpose -> 2x STG.128 per (mf,h) ----
        {
            const size_t obase = ((size_t)b * NK + wm * 64) * PLEN + p0;
            const int q = lane & 3;
            const int krow = lane >> 2;
            #pragma unroll
            for (int mf = 0; mf < 4; mf++) {
                #pragma unroll
                for (int h = 0; h < 2; h++) {
                    float2 v0 = make_float2(acc[mf][0][2*h], acc[mf][0][2*h+1]);
                    float2 v1 = make_float2(acc[mf][1][2*h], acc[mf][1][2*h+1]);
                    float2 v2 = make_float2(acc[mf][2][2*h], acc[mf][2][2*h+1]);
                    float2 v3 = make_float2(acc[mf][3][2*h], acc[mf][3][2*h+1]);
                    xpose_pair(v0, v1, q & 1, 1);
                    xpose_pair(v2, v3, q & 1, 1);
                    xpose_pair(v0, v2, q & 2, 2);
                    xpose_pair(v1, v3, q & 2, 2);
                    size_t o = obase + (size_t)(mf * 16 + krow + 8 * h) * PLEN + q * 8;
                    *(float4*)(out + o)     = make_float4(v0.x, v0.y, v1.x, v1.y);
                    *(float4*)(out + o + 4) = make_float4(v2.x, v2.y, v3.x, v3.y);
                }
            }
        }
    }
}

extern "C" void kernel_launch(void* const* d_in, const int* in_sizes, int n_in,
                              void* d_out, int out_size) {
    static int nsm = 0;
    if (nsm == 0) {
        int dev = 0;
        cudaGetDevice(&dev);
        if (cudaDeviceGetAttribute(&nsm, cudaDevAttrMultiProcessorCount, dev) != cudaSuccess || nsm <= 0)
            nsm = 148;
        cudaFuncSetAttribute(markonv_kernel, cudaFuncAttributeMaxDynamicSharedMemorySize, SMEM_TOTAL);
    }
    markonv_kernel<<<nsm, NTH, SMEM_TOTAL>>>(
        (const float*)d_in[0], (const float*)d_in[1], (float*)d_out);
}